// round 7
// baseline (speedup 1.0000x reference)
#include <cuda_runtime.h>
#include <cuda_fp16.h>

#define NU 100000
#define NI 50000
#define NN 150000            // NU + NI
#define NE 3000000
#define DIM 128
#define D4  32               // DIM / 4 (float4 / uint2 chunks per row)
#define CAP 96               // padded CSR capacity per node (P(deg>96) ~ 1e-32)

// ---- device scratch (allocation-free requirement) ----
// fp16 embedding buffers: [0]=x, [1]=a1, [2]=a2. (a3 is fused into output.)
__device__ uint2 g_h[3][(size_t)NN * D4];
__device__ float  g_inv[NN];
__device__ int    g_cur[NN];
__device__ int    g_csr[(size_t)NN * CAP];
__device__ int    g_is64;

__device__ __forceinline__ __half2 u2h(unsigned u) {
    return *reinterpret_cast<__half2*>(&u);
}

// ---- 0a) detect edge_index element width: int64 stores high word = 0 ----
__global__ void k_detect(const int* __restrict__ ei32) {
    __shared__ int s_or[256];
    int acc = 0;
    for (int i = threadIdx.x; i < 4096; i += 256) acc |= ei32[2 * i + 1];
    s_or[threadIdx.x] = acc;
    __syncthreads();
    for (int d = 128; d > 0; d >>= 1) {
        if (threadIdx.x < d) s_or[threadIdx.x] |= s_or[threadIdx.x + d];
        __syncthreads();
    }
    if (threadIdx.x == 0) g_is64 = (s_or[0] == 0) ? 1 : 0;
}

// ---- 0b) zero cursor array ----
__global__ void k_zero_cur() {
    int i = blockIdx.x * blockDim.x + threadIdx.x;
    if (i < NN) g_cur[i] = 0;
}

// ---- 1) init: g_h[0] = fp16(cat(user, item)) ----
__global__ void k_init_emb(const float4* __restrict__ u4,
                           const float4* __restrict__ i4) {
    const int n4 = NN * D4;
    const int u_n4 = NU * D4;
    for (int i = blockIdx.x * blockDim.x + threadIdx.x; i < n4;
         i += gridDim.x * blockDim.x) {
        float4 v = (i < u_n4) ? u4[i] : i4[i - u_n4];
        __half2 a = __floats2half2_rn(v.x, v.y);
        __half2 b = __floats2half2_rn(v.z, v.w);
        uint2 o;
        o.x = *reinterpret_cast<unsigned*>(&a);
        o.y = *reinterpret_cast<unsigned*>(&b);
        g_h[0][i] = o;
    }
}

// ---- 2) direct scatter into padded CSR (single edge pass, no hist/scan) ----
__global__ void k_scatter(const void* __restrict__ ei) {
    const int is64 = g_is64;
    for (int e = blockIdx.x * blockDim.x + threadIdx.x; e < NE;
         e += gridDim.x * blockDim.x) {
        int src, dst;
        if (is64) {
            src = (int)((const long long*)ei)[e];
            dst = (int)((const long long*)ei)[NE + e];
        } else {
            src = ((const int*)ei)[e];
            dst = ((const int*)ei)[NE + e];
        }
        if ((unsigned)dst < NN && (unsigned)src < NN) {
            int pos = atomicAdd(&g_cur[dst], 1);
            if (pos < CAP) g_csr[(size_t)dst * CAP + pos] = src;
        }
    }
}

// ---- 3) inv_deg from final cursor values ----
__global__ void k_inv() {
    int i = blockIdx.x * blockDim.x + threadIdx.x;
    if (i < NN) {
        int d = g_cur[i];
        g_inv[i] = (d > 0) ? (1.0f / (float)d) : 0.0f;
    }
}

// ---- helper: accumulate one fp16 chunk (4 halves) into fp32 sums ----
__device__ __forceinline__ void acc4(uint2 v, float& sx, float& sy,
                                     float& sz, float& sw) {
    float2 fa = __half22float2(u2h(v.x));
    float2 fb = __half22float2(u2h(v.y));
    sx += fa.x; sy += fa.y; sz += fb.x; sw += fb.y;
}

// ---- 4) propagation layer. FUSE=1: layer 3 + final combine fused.
//         Warp per node, lane handles 4 dims. Depth-2 HADD2 tree per 4 edges. ----
template<int FUSE>
__global__ void k_layer_t(int in_idx,
                          const float4* __restrict__ u4,
                          const float4* __restrict__ i4,
                          float4* __restrict__ out4) {
    const uint2* __restrict__ in = g_h[in_idx];

    int warp = (blockIdx.x * blockDim.x + threadIdx.x) >> 5;
    if (warp >= NN) return;
    int lane = threadIdx.x & 31;

    int deg = g_cur[warp];
    if (deg > CAP) deg = CAP;
    const int* __restrict__ row = g_csr + (size_t)warp * CAP;
    int end = deg;

    float sx = 0.f, sy = 0.f, sz = 0.f, sw = 0.f;
    int e = 0;
    for (; e + 3 < end; e += 4) {
        int s0 = row[e];
        int s1 = row[e + 1];
        int s2 = row[e + 2];
        int s3 = row[e + 3];
        uint2 v0 = in[(size_t)s0 * D4 + lane];
        uint2 v1 = in[(size_t)s1 * D4 + lane];
        uint2 v2 = in[(size_t)s2 * D4 + lane];
        uint2 v3 = in[(size_t)s3 * D4 + lane];
        // depth-2 fp16 tree, one fp32 accumulate per 4 edges
        __half2 a = __hadd2(__hadd2(u2h(v0.x), u2h(v1.x)),
                            __hadd2(u2h(v2.x), u2h(v3.x)));
        __half2 b = __hadd2(__hadd2(u2h(v0.y), u2h(v1.y)),
                            __hadd2(u2h(v2.y), u2h(v3.y)));
        float2 fa = __half22float2(a);
        float2 fb = __half22float2(b);
        sx += fa.x; sy += fa.y; sz += fb.x; sw += fb.y;
    }
    for (; e < end; ++e) {                      // tail: exact fp32 adds
        int s = row[e];
        acc4(in[(size_t)s * D4 + lane], sx, sy, sz, sw);
    }

    float idg = g_inv[warp];
    float rx = sx * idg, ry = sy * idg, rz = sz * idg, rw = sw * idg;

    size_t oi = (size_t)warp * D4 + lane;
    if (FUSE) {
        // out = (x + a1 + a2 + a3) / 4 ; a2 row == in[oi], a3 == r (registers)
        float4 x = (warp < NU) ? u4[oi] : i4[oi - (size_t)NU * D4];
        float tx = x.x + rx, ty = x.y + ry, tz = x.z + rz, tw = x.w + rw;
        acc4(g_h[1][oi], tx, ty, tz, tw);
        acc4(in[oi],     tx, ty, tz, tw);
        float4 r;
        r.x = tx * 0.25f; r.y = ty * 0.25f; r.z = tz * 0.25f; r.w = tw * 0.25f;
        out4[oi] = r;
    } else {
        __half2 ha = __floats2half2_rn(rx, ry);
        __half2 hb = __floats2half2_rn(rz, rw);
        uint2 o;
        o.x = *reinterpret_cast<unsigned*>(&ha);
        o.y = *reinterpret_cast<unsigned*>(&hb);
        g_h[in_idx + 1][oi] = o;
    }
}

extern "C" void kernel_launch(void* const* d_in, const int* in_sizes, int n_in,
                              void* d_out, int out_size) {
    const float4* u4  = (const float4*)d_in[0];
    const float4* i4  = (const float4*)d_in[1];
    const void*   ei  = d_in[2];
    float4*       out = (float4*)d_out;

    // padded-CSR build (no histogram / scan)
    k_detect<<<1, 256>>>((const int*)ei);
    k_zero_cur<<<(NN + 255) / 256, 256>>>();
    k_init_emb<<<2048, 256>>>(u4, i4);
    k_scatter<<<2048, 256>>>(ei);
    k_inv<<<(NN + 255) / 256, 256>>>();

    // 3 propagation layers (warp per node); layer 3 fused with final combine
    const int layer_blocks = (NN * 32 + 255) / 256;
    k_layer_t<0><<<layer_blocks, 256>>>(0, u4, i4, out);  // x  -> a1
    k_layer_t<0><<<layer_blocks, 256>>>(1, u4, i4, out);  // a1 -> a2
    k_layer_t<1><<<layer_blocks, 256>>>(2, u4, i4, out);  // a2 -> out (fused)
}